// round 1
// baseline (speedup 1.0000x reference)
#include <cuda_runtime.h>

// WordHashing: sparse [B=16384 x 30000] (COO, rows sorted) @ W [30000 x 300] + bias, ReLU.
// Inputs (metadata order): sp_rows i32[NNZ], sp_cols i32[NNZ], sp_vals f32[NNZ],
//                          weights f32[30000*300], bias f32[300], batch_size (scalar)
// Output: f32 [B*300]

#define OUT_DIM 300
#define MAX_BATCH 16384

// CSR row offsets scratch (device global: no allocation allowed in kernel_launch).
__device__ int g_row_start[MAX_BATCH + 2];

// Kernel 1: boundary-marking to build row_start from sorted sp_rows.
__global__ void build_row_ptr(const int* __restrict__ rows, int nnz, int batch) {
    int i = blockIdx.x * blockDim.x + threadIdx.x;
    if (i >= nnz) return;
    int r  = rows[i];
    int rp = (i == 0) ? -1 : rows[i - 1];
    // first occurrence of row r (and any empty rows before it) start at i
    for (int q = rp + 1; q <= r; ++q) g_row_start[q] = i;
    // tail: rows after the last nonzero row (and the sentinel) end at nnz
    if (i == nnz - 1) {
        for (int q = r + 1; q <= batch; ++q) g_row_start[q] = nnz;
    }
}

// Kernel 2: one CTA per output row. 160 threads; threads 0..149 own 2 columns (float2).
__global__ __launch_bounds__(160) void spmm_row_kernel(
    const int*   __restrict__ cols,
    const float* __restrict__ vals,
    const float* __restrict__ W,      // [30000 x 300] row-major
    const float* __restrict__ bias,   // [300]
    float*       __restrict__ out)    // [B x 300]
{
    const int row = blockIdx.x;
    const int t   = threadIdx.x;
    if (t >= OUT_DIM / 2) return;          // no block-wide sync used; safe early exit
    const int c2 = 2 * t;                  // columns c2, c2+1

    const int start = g_row_start[row];
    const int end   = g_row_start[row + 1];

    float ax = 0.0f, ay = 0.0f;

    #pragma unroll 4
    for (int i = start; i < end; ++i) {
        const int   c = __ldg(cols + i);   // uniform across warp -> broadcast
        const float v = __ldg(vals + i);
        const float2 w = *reinterpret_cast<const float2*>(W + (size_t)c * OUT_DIM + c2);
        ax = fmaf(v, w.x, ax);
        ay = fmaf(v, w.y, ay);
    }

    const float2 b = *reinterpret_cast<const float2*>(bias + c2);
    float2 o;
    o.x = fmaxf(ax + b.x, 0.0f);
    o.y = fmaxf(ay + b.y, 0.0f);
    *reinterpret_cast<float2*>(out + (size_t)row * OUT_DIM + c2) = o;
}

extern "C" void kernel_launch(void* const* d_in, const int* in_sizes, int n_in,
                              void* d_out, int out_size) {
    const int*   sp_rows = (const int*)  d_in[0];
    const int*   sp_cols = (const int*)  d_in[1];
    const float* sp_vals = (const float*)d_in[2];
    const float* weights = (const float*)d_in[3];
    const float* bias    = (const float*)d_in[4];

    const int nnz   = in_sizes[0];
    const int batch = out_size / OUT_DIM;

    build_row_ptr<<<(nnz + 255) / 256, 256>>>(sp_rows, nnz, batch);
    spmm_row_kernel<<<batch, 160>>>(sp_cols, sp_vals, weights, bias, (float*)d_out);
}